// round 15
// baseline (speedup 1.0000x reference)
#include <cuda_runtime.h>
#include <cuda_fp16.h>
#include <cstdint>

constexpr int ND = 30000, D = 256, R = 8, KW = 2048;
constexpr int NCH    = 36;                    // K chunks of 64 (2304/64)
constexpr int MTILE  = 64;
constexpr int GRID_M = (ND + MTILE - 1) / MTILE;   // 469
constexpr int THREADS = 512;

// smem layout (bytes). 128B row stride + 16B-unit XOR swizzle (col ^ (row&7)).
constexpr int A_OFF    = 0;
constexpr int A_STAGE  = 64 * 128;            // 8192,  3 stages
constexpr int B_OFF    = 3 * A_STAGE;         // 24576
constexpr int B_STAGE  = 512 * 128;           // 65536, 3 stages
constexpr int H_OFF    = B_OFF + 2 * B_STAGE; // 155648 — H aliases B stage 2
constexpr int H_STRIDE = 528;                 // padded (unswizzled), ≡16 mod 128
constexpr int SMEM_T   = B_OFF + 3 * B_STAGE; // 221184

#define SWZ(col, row) ((((col) ^ ((row) & 7)) & 7) << 4)

// device scratch (no allocations allowed)
__device__ __half g_sumh[(size_t)ND * KW];          // fp16 pre-scaled per-(dst,rel) means
__device__ float  g_cnt[ND * R];
__device__ __half g_xdh[(size_t)ND * D];            // x_dst fp16
__device__ __half g_Bh[(size_t)2 * NCH * 256 * 64]; // [L][kc][n][k64] fp16
__device__ __half g_r2h[256 * 256];                 // root2 transposed [n][k]

// ---------------------------------------------------------------------------
__device__ __forceinline__ void mma_f16(float* c, const uint32_t* a,
                                        uint32_t b0, uint32_t b1) {
    asm volatile(
        "mma.sync.aligned.m16n8k16.row.col.f32.f16.f16.f32 "
        "{%0,%1,%2,%3}, {%4,%5,%6,%7}, {%8,%9}, {%0,%1,%2,%3};"
        : "+f"(c[0]), "+f"(c[1]), "+f"(c[2]), "+f"(c[3])
        : "r"(a[0]), "r"(a[1]), "r"(a[2]), "r"(a[3]), "r"(b0), "r"(b1));
}
__device__ __forceinline__ void ldsm_x4(uint32_t* r, uint32_t addr) {
    asm volatile("ldmatrix.sync.aligned.m8n8.x4.shared.b16 {%0,%1,%2,%3}, [%4];"
                 : "=r"(r[0]), "=r"(r[1]), "=r"(r[2]), "=r"(r[3]) : "r"(addr));
}
__device__ __forceinline__ void cp_async16(void* smem_dst, const void* gsrc) {
    uint32_t s = (uint32_t)__cvta_generic_to_shared(smem_dst);
    asm volatile("cp.async.cg.shared.global [%0], [%1], 16;" :: "r"(s), "l"(gsrc));
}
#define CP_COMMIT() asm volatile("cp.async.commit_group;" ::: "memory")
#define CP_WAIT(n)  asm volatile("cp.async.wait_group %0;" :: "n"(n) : "memory")

// ---------------------------------------------------------------------------
// Kernel 0: prep — fp16 weights [L][kc64][n][k64]; root2 [n][k]; x_dst fp16
// ---------------------------------------------------------------------------
__global__ void prep_kernel(const float* __restrict__ w1, const float* __restrict__ r1,
                            const float* __restrict__ w2, const float* __restrict__ r2,
                            const float* __restrict__ xd) {
    int gid = blockIdx.x * blockDim.x + threadIdx.x;
    if (gid < 2 * NCH * 256 * 8) {
        int L   = gid / (NCH * 256 * 8);
        int rem = gid % (NCH * 256 * 8);
        int kc  = rem >> 11;
        int n   = (rem >> 3) & 255;
        int c8  = rem & 7;
        __half h8[8];
#pragma unroll
        for (int j = 0; j < 8; j++) {
            int k = kc * 64 + c8 * 8 + j;
            float x;
            if (L == 0) x = (k < KW) ? w1[(size_t)k * D + n] : r1[(size_t)(k - KW) * D + n];
            else        x = (k < KW) ? w2[(size_t)k * D + n] : 0.f;
            h8[j] = __float2half_rn(x);
        }
        *(uint4*)(g_Bh + ((size_t)(L * NCH + kc) * 256 + n) * 64 + c8 * 8) = *(uint4*)h8;
    }
    if (gid < 256 * 32) {
        int n = gid >> 5, c8 = gid & 31;
        __half h8[8];
#pragma unroll
        for (int j = 0; j < 8; j++)
            h8[j] = __float2half_rn(r2[(size_t)(c8 * 8 + j) * 256 + n]);
        *(uint4*)(g_r2h + (size_t)n * 256 + c8 * 8) = *(uint4*)h8;
    }
    if (gid < ND * D / 4) {
        float4 vd = __ldg((const float4*)xd + gid);
        ((__half2*)g_xdh)[gid * 2]     = __floats2half2_rn(vd.x, vd.y);
        ((__half2*)g_xdh)[gid * 2 + 1] = __floats2half2_rn(vd.z, vd.w);
    }
}

// ---------------------------------------------------------------------------
// Kernel 1: zero fp16 sums + counts, FUSED with edge count pass.
// The 123MB store stream (DRAM-write-bound) overlaps the edge atomics
// (LTS-bound). g_cnt is zeroed first, then a grid-wide sync-free trick is
// NOT needed: counts accumulate into g_cnt which is zeroed by THIS kernel
// before any atomics — ordering enforced by doing cnt-zero in block 0..N
// BEFORE... (can't order across blocks) -> instead g_cnt zeroing stays here
// but count atomics target it only AFTER zero completes. To keep a single
// launch safe, counts go to a SEPARATE accumulator zeroed here first per
// thread before any of this thread's atomics could race: simplest safe form:
// zero g_cnt in a tiny separate kernel BEFORE this fused one (1MB, ~2us),
// then this kernel does g_sumh zero + count atomics concurrently.
// ---------------------------------------------------------------------------
__global__ void zero_cnt_kernel() {
    size_t stride = (size_t)gridDim.x * blockDim.x;
    size_t i = (size_t)blockIdx.x * blockDim.x + threadIdx.x;
    size_t nc4 = (size_t)ND * R / 4;
    for (size_t j = i; j < nc4; j += stride)
        ((float4*)g_cnt)[j] = make_float4(0.f, 0.f, 0.f, 0.f);
}

__global__ void zero_count_kernel(const void* __restrict__ ei,
                                  const void* __restrict__ et, int E) {
    size_t stride = (size_t)gridDim.x * blockDim.x;
    size_t tidg = (size_t)blockIdx.x * blockDim.x + threadIdx.x;

    // count pass (grid-stride over edges) — interleaved with the zero stream
    const int* ei32 = (const int*)ei;
    bool is64 = ((ei32[1] | ei32[3] | ei32[5] | ei32[7]) == 0);
    for (size_t e = tidg; e < (size_t)E; e += stride) {
        long long d, r;
        if (is64) {
            d = ((const long long*)ei)[E + e];
            r = ((const long long*)et)[e];
        } else {
            d = ei32[E + e];
            r = ((const int*)et)[e];
        }
        atomicAdd(&g_cnt[d * R + r], 1.0f);
    }

    // zero the fp16 sums (123MB, DRAM-write-bound)
    uint4 z = make_uint4(0, 0, 0, 0);
    size_t n16 = (size_t)ND * KW / 8;
    for (size_t j = tidg; j < n16; j += stride) ((uint4*)g_sumh)[j] = z;
}

// ---------------------------------------------------------------------------
// Kernel 2: scatter-add PRE-SCALED fp16 (one warp per edge); reads x_src f32.
// ---------------------------------------------------------------------------
__global__ void scatter_kernel(const float* __restrict__ x_src,
                               const void* __restrict__ ei,
                               const void* __restrict__ et, int E) {
    int gw   = (blockIdx.x * blockDim.x + threadIdx.x) >> 5;
    int lane = threadIdx.x & 31;
    if (gw >= E) return;

    const int* ei32 = (const int*)ei;
    bool is64 = ((ei32[1] | ei32[3] | ei32[5] | ei32[7]) == 0);

    long long s, d, r;
    if (is64) {
        const long long* p = (const long long*)ei;
        s = p[gw]; d = p[E + gw]; r = ((const long long*)et)[gw];
    } else {
        s = ei32[gw]; d = ei32[E + gw]; r = ((const int*)et)[gw];
    }

    float c   = __ldg(&g_cnt[d * R + r]);
    float inv = 1.0f / fmaxf(c, 1.0f);

    // 8 f32 per lane = 32B; two float4 loads; convert after f32 scale
    const float4* xr = (const float4*)(x_src + (size_t)s * D) + lane * 2;
    float4 v0 = __ldg(xr);
    float4 v1 = __ldg(xr + 1);
    __half h8[8];
    h8[0] = __float2half_rn(v0.x * inv);
    h8[1] = __float2half_rn(v0.y * inv);
    h8[2] = __float2half_rn(v0.z * inv);
    h8[3] = __float2half_rn(v0.w * inv);
    h8[4] = __float2half_rn(v1.x * inv);
    h8[5] = __float2half_rn(v1.y * inv);
    h8[6] = __float2half_rn(v1.z * inv);
    h8[7] = __float2half_rn(v1.w * inv);
    uint4 w = *(uint4*)h8;

    uint4* dst = (uint4*)(g_sumh + ((size_t)d * R + r) * D) + lane;
    asm volatile("red.global.add.noftz.v4.f16x2 [%0], {%1,%2,%3,%4};"
                 :: "l"(dst), "r"(w.x), "r"(w.y), "r"(w.z), "r"(w.w) : "memory");
}

// ---------------------------------------------------------------------------
// Kernel 3: fully-fused fp16 GEMM (UNCHANGED from round 14 — proven).
// ---------------------------------------------------------------------------
__global__ __launch_bounds__(THREADS, 1)
void fused_all(const float* __restrict__ b1,
               const float* __restrict__ b2,
               float* __restrict__ out) {
    extern __shared__ char smx[];
    uint32_t smb = (uint32_t)__cvta_generic_to_shared(smx);

    int tid = threadIdx.x, wid = tid >> 5, lane = tid & 31;
    int g = lane >> 2, t = lane & 3;
    int L = wid >> 3, sub = wid & 7;
    int wm = (sub >> 2) * 32;       // 0 / 32
    int cb = (sub & 3) * 64;        // 0 / 64 / 128 / 192
    int row0 = blockIdx.x * MTILE;

    int lr = lane & 7, lh = (lane >> 3) & 1, lc = (lane >> 4) & 1;
    int rowA  = wm + lr + lh * 8;
    int rowB  = L * 256 + cb + lr + lc * 8;
    int rowBr = cb + lr + lc * 8;
    uint32_t h_loff = (uint32_t)((wm + lr + lh * 8) * H_STRIDE + lc * 16);

    float acc[2][8][4];
#pragma unroll
    for (int mi = 0; mi < 2; mi++)
#pragma unroll
        for (int nj = 0; nj < 8; nj++)
#pragma unroll
            for (int q = 0; q < 4; q++) acc[mi][nj][q] = 0.f;

    auto ldA = [&](int kc, int s) {
        int row = tid >> 3, c8 = tid & 7;
        int grow = row0 + row;
        if (grow >= ND) grow = 0;               // clamp: finite junk, never stored
        const __half* src = (kc < 32)
            ? g_sumh + (size_t)grow * KW + kc * 64 + c8 * 8
            : g_xdh + (size_t)grow * D + (kc - 32) * 64 + c8 * 8;
        cp_async16(smx + A_OFF + s * A_STAGE + row * 128 + SWZ(c8, row), src);
    };
    auto ldB = [&](int kc, int s) {
#pragma unroll
        for (int i = 0; i < 8; i++) {
            int idx = tid + i * 512;
            int n5 = idx >> 3, c8 = idx & 7;
            int Lx = n5 >> 8, n = n5 & 255;
            cp_async16(smx + B_OFF + s * B_STAGE + n5 * 128 + SWZ(c8, n5),
                       g_Bh + ((size_t)(Lx * NCH + kc) * 256 + n) * 64 + c8 * 8);
        }
    };
    auto ldRootB = [&](int c, int s) {
#pragma unroll
        for (int i = 0; i < 4; i++) {
            int idx = tid + i * 512;
            int n = idx >> 3, c8 = idx & 7;
            cp_async16(smx + B_OFF + s * B_STAGE + n * 128 + SWZ(c8, n),
                       g_r2h + (size_t)n * 256 + c * 64 + c8 * 8);
        }
    };
    auto compute = [&](int s) {
        uint32_t Ab = smb + A_OFF + s * A_STAGE + rowA * 128;
        uint32_t Bb = smb + B_OFF + s * B_STAGE + rowB * 128;
#pragma unroll
        for (int ks = 0; ks < 4; ks++) {
            uint32_t a0[4], a1[4];
            int colA = lc + 2 * ks;
            ldsm_x4(a0, Ab + SWZ(colA, rowA));
            ldsm_x4(a1, Ab + 16 * 128 + SWZ(colA, rowA));
            int colB = lh + 2 * ks;
            uint32_t bsw = SWZ(colB, rowB);
#pragma unroll
            for (int p = 0; p < 4; p++) {
                uint32_t b[4];
                ldsm_x4(b, Bb + p * 16 * 128 + bsw);
                mma_f16(acc[0][2 * p],     a0, b[0], b[1]);
                mma_f16(acc[0][2 * p + 1], a0, b[2], b[3]);
                mma_f16(acc[1][2 * p],     a1, b[0], b[1]);
                mma_f16(acc[1][2 * p + 1], a1, b[2], b[3]);
            }
        }
    };

    // ---- main loop: 36 chunks; S=3, lookahead 2, wait_group(1) ----
    ldB(0, 0); ldA(0, 0); CP_COMMIT();
    ldB(1, 1); ldA(1, 1); CP_COMMIT();
    CP_WAIT(1);
    __syncthreads();

    for (int k = 0; k < NCH; k++) {
        if (k + 2 < NCH) { ldB(k + 2, (k + 2) % 3); ldA(k + 2, (k + 2) % 3); }
        CP_COMMIT();
        compute(k % 3);
        CP_WAIT(1);
        __syncthreads();
    }

    // ---- root2 prologue + layer1 epilogue (h -> smem fp16, aliases B stage 2) ----
    ldRootB(0, 0); CP_COMMIT();
    if (L == 0) {
#pragma unroll
        for (int mi = 0; mi < 2; mi++) {
#pragma unroll
            for (int nj = 0; nj < 8; nj++) {
                int col = cb + nj * 8 + 2 * t;
                float ba = __ldg(&b1[col]), bb = __ldg(&b1[col + 1]);
                __half2 h0 = __floats2half2_rn(fmaxf(acc[mi][nj][0] + ba, 0.f),
                                               fmaxf(acc[mi][nj][1] + bb, 0.f));
                __half2 h1 = __floats2half2_rn(fmaxf(acc[mi][nj][2] + ba, 0.f),
                                               fmaxf(acc[mi][nj][3] + bb, 0.f));
                int r = wm + mi * 16 + g;
                *(__half2*)(smx + H_OFF + r * H_STRIDE + col * 2)       = h0;
                *(__half2*)(smx + H_OFF + (r + 8) * H_STRIDE + col * 2) = h1;
            }
        }
    }
    __syncthreads();

    // ---- root phase: layer2 acc += h @ root2 (4 chunks of K=64, B stages 0/1) ----
    for (int c = 0; c < 4; c++) {
        int s = c & 1;
        CP_WAIT(0);
        __syncthreads();
        if (c + 1 < 4) { ldRootB(c + 1, s ^ 1); CP_COMMIT(); }
        if (L == 1) {
            uint32_t Hb = smb + H_OFF + h_loff + c * 128;
            uint32_t Bb = smb + B_OFF + s * B_STAGE + rowBr * 128;
#pragma unroll
            for (int ks = 0; ks < 4; ks++) {
                uint32_t a0[4], a1[4];
                ldsm_x4(a0, Hb + ks * 32);
                ldsm_x4(a1, Hb + 16 * H_STRIDE + ks * 32);
                int colB = lh + 2 * ks;
                uint32_t bsw = SWZ(colB, rowBr);
#pragma unroll
                for (int p = 0; p < 4; p++) {
                    uint32_t b[4];
                    ldsm_x4(b, Bb + p * 16 * 128 + bsw);
                    mma_f16(acc[0][2 * p],     a0, b[0], b[1]);
                    mma_f16(acc[0][2 * p + 1], a0, b[2], b[3]);
                    mma_f16(acc[1][2 * p],     a1, b[0], b[1]);
                    mma_f16(acc[1][2 * p + 1], a1, b[2], b[3]);
                }
            }
        }
        __syncthreads();
    }

    // ---- layer2 final store ----
    if (L == 1) {
#pragma unroll
        for (int mi = 0; mi < 2; mi++) {
            int r0g = row0 + wm + mi * 16 + g;
#pragma unroll
            for (int nj = 0; nj < 8; nj++) {
                int col = cb + nj * 8 + 2 * t;
                float ba = __ldg(&b2[col]), bb = __ldg(&b2[col + 1]);
                if (r0g < ND)
                    *(float2*)(out + (size_t)r0g * D + col) =
                        make_float2(acc[mi][nj][0] + ba, acc[mi][nj][1] + bb);
                if (r0g + 8 < ND)
                    *(float2*)(out + (size_t)(r0g + 8) * D + col) =
                        make_float2(acc[mi][nj][2] + ba, acc[mi][nj][3] + bb);
            }
        }
    }
}

// ---------------------------------------------------------------------------
extern "C" void kernel_launch(void* const* d_in, const int* in_sizes, int n_in,
                              void* d_out, int out_size) {
    const float* x_src = (const float*)d_in[0];
    const float* x_dst = (const float*)d_in[1];
    const void*  ei    = d_in[2];
    const void*  et    = d_in[3];
    const float* w1    = (const float*)d_in[4];
    const float* root1 = (const float*)d_in[5];
    const float* b1    = (const float*)d_in[6];
    const float* w2    = (const float*)d_in[7];
    const float* root2 = (const float*)d_in[8];
    const float* b2    = (const float*)d_in[9];
    float* out = (float*)d_out;
    int E = in_sizes[3];

    cudaFuncSetAttribute(fused_all, cudaFuncAttributeMaxDynamicSharedMemorySize, SMEM_T);

    zero_cnt_kernel<<<118, 256>>>();                     // 1MB cnt zero (~2us)
    prep_kernel<<<(ND * D / 4 + 255) / 256, 256>>>(w1, root1, w2, root2, x_dst);
    zero_count_kernel<<<2368, 256>>>(ei, et, E);         // 123MB zero + counts
    scatter_kernel<<<(E + 7) / 8, 256>>>(x_src, ei, et, E);

    fused_all<<<GRID_M, THREADS, SMEM_T>>>(b1, b2, out);
}

// round 16
// speedup vs baseline: 1.0176x; 1.0176x over previous
#include <cuda_runtime.h>
#include <cuda_fp16.h>
#include <cstdint>

constexpr int ND = 30000, D = 256, R = 8, KW = 2048;
constexpr int NCH    = 36;                    // K chunks of 64 (2304/64)
constexpr int MTILE  = 64;
constexpr int GRID_M = (ND + MTILE - 1) / MTILE;   // 469
constexpr int THREADS = 512;

// smem layout (bytes). 128B row stride + 16B-unit XOR swizzle (col ^ (row&7)).
constexpr int A_OFF    = 0;
constexpr int A_STAGE  = 64 * 128;            // 8192,  3 stages
constexpr int B_OFF    = 3 * A_STAGE;         // 24576
constexpr int B_STAGE  = 512 * 128;           // 65536, 3 stages
constexpr int H_OFF    = B_OFF + 2 * B_STAGE; // 155648 — H aliases B stage 2
constexpr int H_STRIDE = 528;                 // padded (unswizzled), ≡16 mod 128
constexpr int SMEM_T   = B_OFF + 3 * B_STAGE; // 221184

#define SWZ(col, row) ((((col) ^ ((row) & 7)) & 7) << 4)

// device scratch (no allocations allowed)
__device__ __half g_sumh[(size_t)ND * KW];          // fp16 pre-scaled per-(dst,rel) means
__device__ float  g_cnt[ND * R];
__device__ __half g_xsh[(size_t)ND * D];            // x_src fp16
__device__ __half g_xdh[(size_t)ND * D];            // x_dst fp16
__device__ __half g_Bh[(size_t)2 * NCH * 256 * 64]; // [L][kc][n][k64] fp16
__device__ __half g_r2h[256 * 256];                 // root2 transposed [n][k]

// ---------------------------------------------------------------------------
__device__ __forceinline__ void mma_f16(float* c, const uint32_t* a,
                                        uint32_t b0, uint32_t b1) {
    asm volatile(
        "mma.sync.aligned.m16n8k16.row.col.f32.f16.f16.f32 "
        "{%0,%1,%2,%3}, {%4,%5,%6,%7}, {%8,%9}, {%0,%1,%2,%3};"
        : "+f"(c[0]), "+f"(c[1]), "+f"(c[2]), "+f"(c[3])
        : "r"(a[0]), "r"(a[1]), "r"(a[2]), "r"(a[3]), "r"(b0), "r"(b1));
}
__device__ __forceinline__ void ldsm_x4(uint32_t* r, uint32_t addr) {
    asm volatile("ldmatrix.sync.aligned.m8n8.x4.shared.b16 {%0,%1,%2,%3}, [%4];"
                 : "=r"(r[0]), "=r"(r[1]), "=r"(r[2]), "=r"(r[3]) : "r"(addr));
}
__device__ __forceinline__ void cp_async16(void* smem_dst, const void* gsrc) {
    uint32_t s = (uint32_t)__cvta_generic_to_shared(smem_dst);
    asm volatile("cp.async.cg.shared.global [%0], [%1], 16;" :: "r"(s), "l"(gsrc));
}
#define CP_COMMIT() asm volatile("cp.async.commit_group;" ::: "memory")
#define CP_WAIT(n)  asm volatile("cp.async.wait_group %0;" :: "n"(n) : "memory")

// ---------------------------------------------------------------------------
// Kernel 0: prep — fp16 weights [L][kc64][n][k64]; root2 [n][k]; x_src/x_dst fp16
// ---------------------------------------------------------------------------
__global__ void prep_kernel(const float* __restrict__ w1, const float* __restrict__ r1,
                            const float* __restrict__ w2, const float* __restrict__ r2,
                            const float* __restrict__ xs, const float* __restrict__ xd) {
    int gid = blockIdx.x * blockDim.x + threadIdx.x;
    if (gid < 2 * NCH * 256 * 8) {
        int L   = gid / (NCH * 256 * 8);
        int rem = gid % (NCH * 256 * 8);
        int kc  = rem >> 11;
        int n   = (rem >> 3) & 255;
        int c8  = rem & 7;
        __half h8[8];
#pragma unroll
        for (int j = 0; j < 8; j++) {
            int k = kc * 64 + c8 * 8 + j;
            float x;
            if (L == 0) x = (k < KW) ? w1[(size_t)k * D + n] : r1[(size_t)(k - KW) * D + n];
            else        x = (k < KW) ? w2[(size_t)k * D + n] : 0.f;
            h8[j] = __float2half_rn(x);
        }
        *(uint4*)(g_Bh + ((size_t)(L * NCH + kc) * 256 + n) * 64 + c8 * 8) = *(uint4*)h8;
    }
    if (gid < 256 * 32) {
        int n = gid >> 5, c8 = gid & 31;
        __half h8[8];
#pragma unroll
        for (int j = 0; j < 8; j++)
            h8[j] = __float2half_rn(r2[(size_t)(c8 * 8 + j) * 256 + n]);
        *(uint4*)(g_r2h + (size_t)n * 256 + c8 * 8) = *(uint4*)h8;
    }
    if (gid < ND * D / 4) {
        float4 vs = __ldg((const float4*)xs + gid);
        float4 vd = __ldg((const float4*)xd + gid);
        ((__half2*)g_xsh)[gid * 2]     = __floats2half2_rn(vs.x, vs.y);
        ((__half2*)g_xsh)[gid * 2 + 1] = __floats2half2_rn(vs.z, vs.w);
        ((__half2*)g_xdh)[gid * 2]     = __floats2half2_rn(vd.x, vd.y);
        ((__half2*)g_xdh)[gid * 2 + 1] = __floats2half2_rn(vd.z, vd.w);
    }
}

// ---------------------------------------------------------------------------
// Kernel 1a: zero counts (tiny; must precede the fused zero+count kernel)
// ---------------------------------------------------------------------------
__global__ void zero_cnt_kernel() {
    size_t stride = (size_t)gridDim.x * blockDim.x;
    size_t i = (size_t)blockIdx.x * blockDim.x + threadIdx.x;
    size_t nc4 = (size_t)ND * R / 4;
    for (size_t j = i; j < nc4; j += stride)
        ((float4*)g_cnt)[j] = make_float4(0.f, 0.f, 0.f, 0.f);
}

// ---------------------------------------------------------------------------
// Kernel 1b: FUSED — edge count atomics (LTS-bound) overlap the 123MB
// fp16-sum zero stream (DRAM-write-bound).
// ---------------------------------------------------------------------------
__global__ void zero_count_kernel(const void* __restrict__ ei,
                                  const void* __restrict__ et, int E) {
    size_t stride = (size_t)gridDim.x * blockDim.x;
    size_t tidg = (size_t)blockIdx.x * blockDim.x + threadIdx.x;

    const int* ei32 = (const int*)ei;
    bool is64 = ((ei32[1] | ei32[3] | ei32[5] | ei32[7]) == 0);
    for (size_t e = tidg; e < (size_t)E; e += stride) {
        long long d, r;
        if (is64) {
            d = ((const long long*)ei)[E + e];
            r = ((const long long*)et)[e];
        } else {
            d = ei32[E + e];
            r = ((const int*)et)[e];
        }
        atomicAdd(&g_cnt[d * R + r], 1.0f);
    }

    uint4 z = make_uint4(0, 0, 0, 0);
    size_t n16 = (size_t)ND * KW / 8;
    for (size_t j = tidg; j < n16; j += stride) ((uint4*)g_sumh)[j] = z;
}

// ---------------------------------------------------------------------------
// Kernel 2: scatter-add PRE-SCALED fp16 (one warp per edge) — round-14 proven:
// fp16 gather from g_xsh, f32 scale, fp16 round, v4.f16x2 reduction.
// ---------------------------------------------------------------------------
__global__ void scatter_kernel(const void* __restrict__ ei,
                               const void* __restrict__ et, int E) {
    int gw   = (blockIdx.x * blockDim.x + threadIdx.x) >> 5;
    int lane = threadIdx.x & 31;
    if (gw >= E) return;

    const int* ei32 = (const int*)ei;
    bool is64 = ((ei32[1] | ei32[3] | ei32[5] | ei32[7]) == 0);

    long long s, d, r;
    if (is64) {
        const long long* p = (const long long*)ei;
        s = p[gw]; d = p[E + gw]; r = ((const long long*)et)[gw];
    } else {
        s = ei32[gw]; d = ei32[E + gw]; r = ((const int*)et)[gw];
    }

    float c   = __ldg(&g_cnt[d * R + r]);
    float inv = 1.0f / fmaxf(c, 1.0f);

    uint4 v = __ldg((const uint4*)(g_xsh + (size_t)s * D) + lane);
    const __half* hv = (const __half*)&v;
    __half h8[8];
#pragma unroll
    for (int j = 0; j < 8; j++)
        h8[j] = __float2half_rn(__half2float(hv[j]) * inv);
    uint4 w = *(uint4*)h8;

    uint4* dst = (uint4*)(g_sumh + ((size_t)d * R + r) * D) + lane;
    asm volatile("red.global.add.noftz.v4.f16x2 [%0], {%1,%2,%3,%4};"
                 :: "l"(dst), "r"(w.x), "r"(w.y), "r"(w.z), "r"(w.w) : "memory");
}

// ---------------------------------------------------------------------------
// Kernel 3: fully-fused fp16 GEMM (UNCHANGED round-14 proven version).
// ---------------------------------------------------------------------------
__global__ __launch_bounds__(THREADS, 1)
void fused_all(const float* __restrict__ b1,
               const float* __restrict__ b2,
               float* __restrict__ out) {
    extern __shared__ char smx[];
    uint32_t smb = (uint32_t)__cvta_generic_to_shared(smx);

    int tid = threadIdx.x, wid = tid >> 5, lane = tid & 31;
    int g = lane >> 2, t = lane & 3;
    int L = wid >> 3, sub = wid & 7;
    int wm = (sub >> 2) * 32;       // 0 / 32
    int cb = (sub & 3) * 64;        // 0 / 64 / 128 / 192
    int row0 = blockIdx.x * MTILE;

    int lr = lane & 7, lh = (lane >> 3) & 1, lc = (lane >> 4) & 1;
    int rowA  = wm + lr + lh * 8;
    int rowB  = L * 256 + cb + lr + lc * 8;
    int rowBr = cb + lr + lc * 8;
    uint32_t h_loff = (uint32_t)((wm + lr + lh * 8) * H_STRIDE + lc * 16);

    float acc[2][8][4];
#pragma unroll
    for (int mi = 0; mi < 2; mi++)
#pragma unroll
        for (int nj = 0; nj < 8; nj++)
#pragma unroll
            for (int q = 0; q < 4; q++) acc[mi][nj][q] = 0.f;

    auto ldA = [&](int kc, int s) {
        int row = tid >> 3, c8 = tid & 7;
        int grow = row0 + row;
        if (grow >= ND) grow = 0;               // clamp: finite junk, never stored
        const __half* src = (kc < 32)
            ? g_sumh + (size_t)grow * KW + kc * 64 + c8 * 8
            : g_xdh + (size_t)grow * D + (kc - 32) * 64 + c8 * 8;
        cp_async16(smx + A_OFF + s * A_STAGE + row * 128 + SWZ(c8, row), src);
    };
    auto ldB = [&](int kc, int s) {
#pragma unroll
        for (int i = 0; i < 8; i++) {
            int idx = tid + i * 512;
            int n5 = idx >> 3, c8 = idx & 7;
            int Lx = n5 >> 8, n = n5 & 255;
            cp_async16(smx + B_OFF + s * B_STAGE + n5 * 128 + SWZ(c8, n5),
                       g_Bh + ((size_t)(Lx * NCH + kc) * 256 + n) * 64 + c8 * 8);
        }
    };
    auto ldRootB = [&](int c, int s) {
#pragma unroll
        for (int i = 0; i < 4; i++) {
            int idx = tid + i * 512;
            int n = idx >> 3, c8 = idx & 7;
            cp_async16(smx + B_OFF + s * B_STAGE + n * 128 + SWZ(c8, n),
                       g_r2h + (size_t)n * 256 + c * 64 + c8 * 8);
        }
    };
    auto compute = [&](int s) {
        uint32_t Ab = smb + A_OFF + s * A_STAGE + rowA * 128;
        uint32_t Bb = smb + B_OFF + s * B_STAGE + rowB * 128;
#pragma unroll
        for (int ks = 0; ks < 4; ks++) {
            uint32_t a0[4], a1[4];
            int colA = lc + 2 * ks;
            ldsm_x4(a0, Ab + SWZ(colA, rowA));
            ldsm_x4(a1, Ab + 16 * 128 + SWZ(colA, rowA));
            int colB = lh + 2 * ks;
            uint32_t bsw = SWZ(colB, rowB);
#pragma unroll
            for (int p = 0; p < 4; p++) {
                uint32_t b[4];
                ldsm_x4(b, Bb + p * 16 * 128 + bsw);
                mma_f16(acc[0][2 * p],     a0, b[0], b[1]);
                mma_f16(acc[0][2 * p + 1], a0, b[2], b[3]);
                mma_f16(acc[1][2 * p],     a1, b[0], b[1]);
                mma_f16(acc[1][2 * p + 1], a1, b[2], b[3]);
            }
        }
    };

    // ---- main loop: 36 chunks; S=3, lookahead 2, wait_group(1) ----
    ldB(0, 0); ldA(0, 0); CP_COMMIT();
    ldB(1, 1); ldA(1, 1); CP_COMMIT();
    CP_WAIT(1);
    __syncthreads();

    for (int k = 0; k < NCH; k++) {
        if (k + 2 < NCH) { ldB(k + 2, (k + 2) % 3); ldA(k + 2, (k + 2) % 3); }
        CP_COMMIT();
        compute(k % 3);
        CP_WAIT(1);
        __syncthreads();
    }

    // ---- root2 prologue + layer1 epilogue (h -> smem fp16, aliases B stage 2) ----
    ldRootB(0, 0); CP_COMMIT();
    if (L == 0) {
#pragma unroll
        for (int mi = 0; mi < 2; mi++) {
#pragma unroll
            for (int nj = 0; nj < 8; nj++) {
                int col = cb + nj * 8 + 2 * t;
                float ba = __ldg(&b1[col]), bb = __ldg(&b1[col + 1]);
                __half2 h0 = __floats2half2_rn(fmaxf(acc[mi][nj][0] + ba, 0.f),
                                               fmaxf(acc[mi][nj][1] + bb, 0.f));
                __half2 h1 = __floats2half2_rn(fmaxf(acc[mi][nj][2] + ba, 0.f),
                                               fmaxf(acc[mi][nj][3] + bb, 0.f));
                int r = wm + mi * 16 + g;
                *(__half2*)(smx + H_OFF + r * H_STRIDE + col * 2)       = h0;
                *(__half2*)(smx + H_OFF + (r + 8) * H_STRIDE + col * 2) = h1;
            }
        }
    }
    __syncthreads();

    // ---- root phase: layer2 acc += h @ root2 (4 chunks of K=64, B stages 0/1) ----
    for (int c = 0; c < 4; c++) {
        int s = c & 1;
        CP_WAIT(0);
        __syncthreads();
        if (c + 1 < 4) { ldRootB(c + 1, s ^ 1); CP_COMMIT(); }
        if (L == 1) {
            uint32_t Hb = smb + H_OFF + h_loff + c * 128;
            uint32_t Bb = smb + B_OFF + s * B_STAGE + rowBr * 128;
#pragma unroll
            for (int ks = 0; ks < 4; ks++) {
                uint32_t a0[4], a1[4];
                ldsm_x4(a0, Hb + ks * 32);
                ldsm_x4(a1, Hb + 16 * H_STRIDE + ks * 32);
                int colB = lh + 2 * ks;
                uint32_t bsw = SWZ(colB, rowBr);
#pragma unroll
                for (int p = 0; p < 4; p++) {
                    uint32_t b[4];
                    ldsm_x4(b, Bb + p * 16 * 128 + bsw);
                    mma_f16(acc[0][2 * p],     a0, b[0], b[1]);
                    mma_f16(acc[0][2 * p + 1], a0, b[2], b[3]);
                    mma_f16(acc[1][2 * p],     a1, b[0], b[1]);
                    mma_f16(acc[1][2 * p + 1], a1, b[2], b[3]);
                }
            }
        }
        __syncthreads();
    }

    // ---- layer2 final store ----
    if (L == 1) {
#pragma unroll
        for (int mi = 0; mi < 2; mi++) {
            int r0g = row0 + wm + mi * 16 + g;
#pragma unroll
            for (int nj = 0; nj < 8; nj++) {
                int col = cb + nj * 8 + 2 * t;
                float ba = __ldg(&b2[col]), bb = __ldg(&b2[col + 1]);
                if (r0g < ND)
                    *(float2*)(out + (size_t)r0g * D + col) =
                        make_float2(acc[mi][nj][0] + ba, acc[mi][nj][1] + bb);
                if (r0g + 8 < ND)
                    *(float2*)(out + (size_t)(r0g + 8) * D + col) =
                        make_float2(acc[mi][nj][2] + ba, acc[mi][nj][3] + bb);
            }
        }
    }
}

// ---------------------------------------------------------------------------
extern "C" void kernel_launch(void* const* d_in, const int* in_sizes, int n_in,
                              void* d_out, int out_size) {
    const float* x_src = (const float*)d_in[0];
    const float* x_dst = (const float*)d_in[1];
    const void*  ei    = d_in[2];
    const void*  et    = d_in[3];
    const float* w1    = (const float*)d_in[4];
    const float* root1 = (const float*)d_in[5];
    const float* b1    = (const float*)d_in[6];
    const float* w2    = (const float*)d_in[7];
    const float* root2 = (const float*)d_in[8];
    const float* b2    = (const float*)d_in[9];
    float* out = (float*)d_out;
    int E = in_sizes[3];

    cudaFuncSetAttribute(fused_all, cudaFuncAttributeMaxDynamicSharedMemorySize, SMEM_T);

    zero_cnt_kernel<<<118, 256>>>();                     // 1MB cnt zero (~2us)
    prep_kernel<<<(ND * D / 4 + 255) / 256, 256>>>(w1, root1, w2, root2, x_src, x_dst);
    zero_count_kernel<<<2368, 256>>>(ei, et, E);         // 123MB zero + counts
    scatter_kernel<<<(E + 7) / 8, 256>>>(ei, et, E);

    fused_all<<<GRID_M, THREADS, SMEM_T>>>(b1, b2, out);
}

// round 17
// speedup vs baseline: 1.0258x; 1.0080x over previous
#include <cuda_runtime.h>
#include <cuda_fp16.h>
#include <cstdint>

constexpr int ND = 30000, D = 256, R = 8, KW = 2048;
constexpr int NCH    = 36;                    // K chunks of 64 (2304/64)
constexpr int MTILE  = 64;
constexpr int GRID_M = (ND + MTILE - 1) / MTILE;   // 469
constexpr int THREADS = 512;

// smem layout (bytes). 128B row stride + 16B-unit XOR swizzle (col ^ (row&7)).
constexpr int A_OFF    = 0;
constexpr int A_STAGE  = 64 * 128;            // 8192,  3 stages
constexpr int B_OFF    = 3 * A_STAGE;         // 24576
constexpr int B_STAGE  = 512 * 128;           // 65536, 3 stages
constexpr int H_OFF    = B_OFF + 2 * B_STAGE; // 155648 — H aliases B stage 2
constexpr int H_STRIDE = 528;                 // padded (unswizzled), ≡16 mod 128
constexpr int SMEM_T   = B_OFF + 3 * B_STAGE; // 221184

#define SWZ(col, row) ((((col) ^ ((row) & 7)) & 7) << 4)

// device scratch (no allocations allowed)
__device__ __half g_sumh[(size_t)ND * KW];          // fp16 pre-scaled per-(dst,rel) means
__device__ float  g_cnt[ND * R];
__device__ __half g_xsh[(size_t)ND * D];            // x_src fp16
__device__ __half g_xdh[(size_t)ND * D];            // x_dst fp16
__device__ __half g_Bh[(size_t)2 * NCH * 256 * 64]; // [L][kc][n][k64] fp16
__device__ __half g_r2h[256 * 256];                 // root2 transposed [n][k]

// ---------------------------------------------------------------------------
__device__ __forceinline__ void mma_f16(float* c, const uint32_t* a,
                                        uint32_t b0, uint32_t b1) {
    asm volatile(
        "mma.sync.aligned.m16n8k16.row.col.f32.f16.f16.f32 "
        "{%0,%1,%2,%3}, {%4,%5,%6,%7}, {%8,%9}, {%0,%1,%2,%3};"
        : "+f"(c[0]), "+f"(c[1]), "+f"(c[2]), "+f"(c[3])
        : "r"(a[0]), "r"(a[1]), "r"(a[2]), "r"(a[3]), "r"(b0), "r"(b1));
}
__device__ __forceinline__ void ldsm_x4(uint32_t* r, uint32_t addr) {
    asm volatile("ldmatrix.sync.aligned.m8n8.x4.shared.b16 {%0,%1,%2,%3}, [%4];"
                 : "=r"(r[0]), "=r"(r[1]), "=r"(r[2]), "=r"(r[3]) : "r"(addr));
}
__device__ __forceinline__ void cp_async16(void* smem_dst, const void* gsrc) {
    uint32_t s = (uint32_t)__cvta_generic_to_shared(smem_dst);
    asm volatile("cp.async.cg.shared.global [%0], [%1], 16;" :: "r"(s), "l"(gsrc));
}
#define CP_COMMIT() asm volatile("cp.async.commit_group;" ::: "memory")
#define CP_WAIT(n)  asm volatile("cp.async.wait_group %0;" :: "n"(n) : "memory")

// ---------------------------------------------------------------------------
// Kernel 0a: zero counts (tiny; must precede the mega kernel's count atomics)
// ---------------------------------------------------------------------------
__global__ void zero_cnt_kernel() {
    size_t stride = (size_t)gridDim.x * blockDim.x;
    size_t i = (size_t)blockIdx.x * blockDim.x + threadIdx.x;
    size_t nc4 = (size_t)ND * R / 4;
    for (size_t j = i; j < nc4; j += stride)
        ((float4*)g_cnt)[j] = make_float4(0.f, 0.f, 0.f, 0.f);
}

// ---------------------------------------------------------------------------
// Kernel 0b: MEGA prep — all independent pre-work in ONE kernel so the
// different bottlenecks overlap: edge-count atomics (LTS), weight/x fp16
// conversion (DRAM read + cvt), 123MB sum zero (DRAM write).
// ---------------------------------------------------------------------------
__global__ void mega_prep(const float* __restrict__ w1, const float* __restrict__ r1,
                          const float* __restrict__ w2, const float* __restrict__ r2,
                          const float* __restrict__ xs, const float* __restrict__ xd,
                          const void* __restrict__ ei, const void* __restrict__ et,
                          int E) {
    size_t stride = (size_t)gridDim.x * blockDim.x;
    size_t tidg = (size_t)blockIdx.x * blockDim.x + threadIdx.x;

    // 1) edge counts (long-latency atomics issued first)
    const int* ei32 = (const int*)ei;
    bool is64 = ((ei32[1] | ei32[3] | ei32[5] | ei32[7]) == 0);
    for (size_t e = tidg; e < (size_t)E; e += stride) {
        long long d, r;
        if (is64) {
            d = ((const long long*)ei)[E + e];
            r = ((const long long*)et)[e];
        } else {
            d = ei32[E + e];
            r = ((const int*)et)[e];
        }
        atomicAdd(&g_cnt[d * R + r], 1.0f);
    }

    // 2) weights -> fp16 transposed chunk tiles
    for (size_t g = tidg; g < (size_t)2 * NCH * 256 * 8; g += stride) {
        int L   = (int)(g / (NCH * 256 * 8));
        int rem = (int)(g % (NCH * 256 * 8));
        int kc  = rem >> 11;
        int n   = (rem >> 3) & 255;
        int c8  = rem & 7;
        __half h8[8];
#pragma unroll
        for (int j = 0; j < 8; j++) {
            int k = kc * 64 + c8 * 8 + j;
            float x;
            if (L == 0) x = (k < KW) ? w1[(size_t)k * D + n] : r1[(size_t)(k - KW) * D + n];
            else        x = (k < KW) ? w2[(size_t)k * D + n] : 0.f;
            h8[j] = __float2half_rn(x);
        }
        *(uint4*)(g_Bh + ((size_t)(L * NCH + kc) * 256 + n) * 64 + c8 * 8) = *(uint4*)h8;
    }

    // 3) root2 -> fp16 transposed
    for (size_t g = tidg; g < 256 * 32; g += stride) {
        int n = (int)(g >> 5), c8 = (int)(g & 31);
        __half h8[8];
#pragma unroll
        for (int j = 0; j < 8; j++)
            h8[j] = __float2half_rn(r2[(size_t)(c8 * 8 + j) * 256 + n]);
        *(uint4*)(g_r2h + (size_t)n * 256 + c8 * 8) = *(uint4*)h8;
    }

    // 4) x_src / x_dst -> fp16
    for (size_t g = tidg; g < (size_t)ND * D / 4; g += stride) {
        float4 vs = __ldg((const float4*)xs + g);
        float4 vd = __ldg((const float4*)xd + g);
        ((__half2*)g_xsh)[g * 2]     = __floats2half2_rn(vs.x, vs.y);
        ((__half2*)g_xsh)[g * 2 + 1] = __floats2half2_rn(vs.z, vs.w);
        ((__half2*)g_xdh)[g * 2]     = __floats2half2_rn(vd.x, vd.y);
        ((__half2*)g_xdh)[g * 2 + 1] = __floats2half2_rn(vd.z, vd.w);
    }

    // 5) zero the fp16 sums (123MB DRAM-write stream)
    uint4 z = make_uint4(0, 0, 0, 0);
    size_t n16 = (size_t)ND * KW / 8;
    for (size_t j = tidg; j < n16; j += stride) ((uint4*)g_sumh)[j] = z;
}

// ---------------------------------------------------------------------------
// Kernel 1: scatter-add PRE-SCALED fp16 (one warp per edge) — proven:
// fp16 gather from g_xsh, f32 scale, fp16 round, v4.f16x2 reduction.
// ---------------------------------------------------------------------------
__global__ void scatter_kernel(const void* __restrict__ ei,
                               const void* __restrict__ et, int E) {
    int gw   = (blockIdx.x * blockDim.x + threadIdx.x) >> 5;
    int lane = threadIdx.x & 31;
    if (gw >= E) return;

    const int* ei32 = (const int*)ei;
    bool is64 = ((ei32[1] | ei32[3] | ei32[5] | ei32[7]) == 0);

    long long s, d, r;
    if (is64) {
        const long long* p = (const long long*)ei;
        s = p[gw]; d = p[E + gw]; r = ((const long long*)et)[gw];
    } else {
        s = ei32[gw]; d = ei32[E + gw]; r = ((const int*)et)[gw];
    }

    float c   = __ldg(&g_cnt[d * R + r]);
    float inv = 1.0f / fmaxf(c, 1.0f);

    uint4 v = __ldg((const uint4*)(g_xsh + (size_t)s * D) + lane);
    const __half* hv = (const __half*)&v;
    __half h8[8];
#pragma unroll
    for (int j = 0; j < 8; j++)
        h8[j] = __float2half_rn(__half2float(hv[j]) * inv);
    uint4 w = *(uint4*)h8;

    uint4* dst = (uint4*)(g_sumh + ((size_t)d * R + r) * D) + lane;
    asm volatile("red.global.add.noftz.v4.f16x2 [%0], {%1,%2,%3,%4};"
                 :: "l"(dst), "r"(w.x), "r"(w.y), "r"(w.z), "r"(w.w) : "memory");
}

// ---------------------------------------------------------------------------
// Kernel 2: fully-fused fp16 GEMM (UNCHANGED round-14 proven version).
// ---------------------------------------------------------------------------
__global__ __launch_bounds__(THREADS, 1)
void fused_all(const float* __restrict__ b1,
               const float* __restrict__ b2,
               float* __restrict__ out) {
    extern __shared__ char smx[];
    uint32_t smb = (uint32_t)__cvta_generic_to_shared(smx);

    int tid = threadIdx.x, wid = tid >> 5, lane = tid & 31;
    int g = lane >> 2, t = lane & 3;
    int L = wid >> 3, sub = wid & 7;
    int wm = (sub >> 2) * 32;       // 0 / 32
    int cb = (sub & 3) * 64;        // 0 / 64 / 128 / 192
    int row0 = blockIdx.x * MTILE;

    int lr = lane & 7, lh = (lane >> 3) & 1, lc = (lane >> 4) & 1;
    int rowA  = wm + lr + lh * 8;
    int rowB  = L * 256 + cb + lr + lc * 8;
    int rowBr = cb + lr + lc * 8;
    uint32_t h_loff = (uint32_t)((wm + lr + lh * 8) * H_STRIDE + lc * 16);

    float acc[2][8][4];
#pragma unroll
    for (int mi = 0; mi < 2; mi++)
#pragma unroll
        for (int nj = 0; nj < 8; nj++)
#pragma unroll
            for (int q = 0; q < 4; q++) acc[mi][nj][q] = 0.f;

    auto ldA = [&](int kc, int s) {
        int row = tid >> 3, c8 = tid & 7;
        int grow = row0 + row;
        if (grow >= ND) grow = 0;               // clamp: finite junk, never stored
        const __half* src = (kc < 32)
            ? g_sumh + (size_t)grow * KW + kc * 64 + c8 * 8
            : g_xdh + (size_t)grow * D + (kc - 32) * 64 + c8 * 8;
        cp_async16(smx + A_OFF + s * A_STAGE + row * 128 + SWZ(c8, row), src);
    };
    auto ldB = [&](int kc, int s) {
#pragma unroll
        for (int i = 0; i < 8; i++) {
            int idx = tid + i * 512;
            int n5 = idx >> 3, c8 = idx & 7;
            int Lx = n5 >> 8, n = n5 & 255;
            cp_async16(smx + B_OFF + s * B_STAGE + n5 * 128 + SWZ(c8, n5),
                       g_Bh + ((size_t)(Lx * NCH + kc) * 256 + n) * 64 + c8 * 8);
        }
    };
    auto ldRootB = [&](int c, int s) {
#pragma unroll
        for (int i = 0; i < 4; i++) {
            int idx = tid + i * 512;
            int n = idx >> 3, c8 = idx & 7;
            cp_async16(smx + B_OFF + s * B_STAGE + n * 128 + SWZ(c8, n),
                       g_r2h + (size_t)n * 256 + c * 64 + c8 * 8);
        }
    };
    auto compute = [&](int s) {
        uint32_t Ab = smb + A_OFF + s * A_STAGE + rowA * 128;
        uint32_t Bb = smb + B_OFF + s * B_STAGE + rowB * 128;
#pragma unroll
        for (int ks = 0; ks < 4; ks++) {
            uint32_t a0[4], a1[4];
            int colA = lc + 2 * ks;
            ldsm_x4(a0, Ab + SWZ(colA, rowA));
            ldsm_x4(a1, Ab + 16 * 128 + SWZ(colA, rowA));
            int colB = lh + 2 * ks;
            uint32_t bsw = SWZ(colB, rowB);
#pragma unroll
            for (int p = 0; p < 4; p++) {
                uint32_t b[4];
                ldsm_x4(b, Bb + p * 16 * 128 + bsw);
                mma_f16(acc[0][2 * p],     a0, b[0], b[1]);
                mma_f16(acc[0][2 * p + 1], a0, b[2], b[3]);
                mma_f16(acc[1][2 * p],     a1, b[0], b[1]);
                mma_f16(acc[1][2 * p + 1], a1, b[2], b[3]);
            }
        }
    };

    // ---- main loop: 36 chunks; S=3, lookahead 2, wait_group(1) ----
    ldB(0, 0); ldA(0, 0); CP_COMMIT();
    ldB(1, 1); ldA(1, 1); CP_COMMIT();
    CP_WAIT(1);
    __syncthreads();

    for (int k = 0; k < NCH; k++) {
        if (k + 2 < NCH) { ldB(k + 2, (k + 2) % 3); ldA(k + 2, (k + 2) % 3); }
        CP_COMMIT();
        compute(k % 3);
        CP_WAIT(1);
        __syncthreads();
    }

    // ---- root2 prologue + layer1 epilogue (h -> smem fp16, aliases B stage 2) ----
    ldRootB(0, 0); CP_COMMIT();
    if (L == 0) {
#pragma unroll
        for (int mi = 0; mi < 2; mi++) {
#pragma unroll
            for (int nj = 0; nj < 8; nj++) {
                int col = cb + nj * 8 + 2 * t;
                float ba = __ldg(&b1[col]), bb = __ldg(&b1[col + 1]);
                __half2 h0 = __floats2half2_rn(fmaxf(acc[mi][nj][0] + ba, 0.f),
                                               fmaxf(acc[mi][nj][1] + bb, 0.f));
                __half2 h1 = __floats2half2_rn(fmaxf(acc[mi][nj][2] + ba, 0.f),
                                               fmaxf(acc[mi][nj][3] + bb, 0.f));
                int r = wm + mi * 16 + g;
                *(__half2*)(smx + H_OFF + r * H_STRIDE + col * 2)       = h0;
                *(__half2*)(smx + H_OFF + (r + 8) * H_STRIDE + col * 2) = h1;
            }
        }
    }
    __syncthreads();

    // ---- root phase: layer2 acc += h @ root2 (4 chunks of K=64, B stages 0/1) ----
    for (int c = 0; c < 4; c++) {
        int s = c & 1;
        CP_WAIT(0);
        __syncthreads();
        if (c + 1 < 4) { ldRootB(c + 1, s ^ 1); CP_COMMIT(); }
        if (L == 1) {
            uint32_t Hb = smb + H_OFF + h_loff + c * 128;
            uint32_t Bb = smb + B_OFF + s * B_STAGE + rowBr * 128;
#pragma unroll
            for (int ks = 0; ks < 4; ks++) {
                uint32_t a0[4], a1[4];
                ldsm_x4(a0, Hb + ks * 32);
                ldsm_x4(a1, Hb + 16 * H_STRIDE + ks * 32);
                int colB = lh + 2 * ks;
                uint32_t bsw = SWZ(colB, rowBr);
#pragma unroll
                for (int p = 0; p < 4; p++) {
                    uint32_t b[4];
                    ldsm_x4(b, Bb + p * 16 * 128 + bsw);
                    mma_f16(acc[0][2 * p],     a0, b[0], b[1]);
                    mma_f16(acc[0][2 * p + 1], a0, b[2], b[3]);
                    mma_f16(acc[1][2 * p],     a1, b[0], b[1]);
                    mma_f16(acc[1][2 * p + 1], a1, b[2], b[3]);
                }
            }
        }
        __syncthreads();
    }

    // ---- layer2 final store ----
    if (L == 1) {
#pragma unroll
        for (int mi = 0; mi < 2; mi++) {
            int r0g = row0 + wm + mi * 16 + g;
#pragma unroll
            for (int nj = 0; nj < 8; nj++) {
                int col = cb + nj * 8 + 2 * t;
                float ba = __ldg(&b2[col]), bb = __ldg(&b2[col + 1]);
                if (r0g < ND)
                    *(float2*)(out + (size_t)r0g * D + col) =
                        make_float2(acc[mi][nj][0] + ba, acc[mi][nj][1] + bb);
                if (r0g + 8 < ND)
                    *(float2*)(out + (size_t)(r0g + 8) * D + col) =
                        make_float2(acc[mi][nj][2] + ba, acc[mi][nj][3] + bb);
            }
        }
    }
}

// ---------------------------------------------------------------------------
extern "C" void kernel_launch(void* const* d_in, const int* in_sizes, int n_in,
                              void* d_out, int out_size) {
    const float* x_src = (const float*)d_in[0];
    const float* x_dst = (const float*)d_in[1];
    const void*  ei    = d_in[2];
    const void*  et    = d_in[3];
    const float* w1    = (const float*)d_in[4];
    const float* root1 = (const float*)d_in[5];
    const float* b1    = (const float*)d_in[6];
    const float* w2    = (const float*)d_in[7];
    const float* root2 = (const float*)d_in[8];
    const float* b2    = (const float*)d_in[9];
    float* out = (float*)d_out;
    int E = in_sizes[3];

    cudaFuncSetAttribute(fused_all, cudaFuncAttributeMaxDynamicSharedMemorySize, SMEM_T);

    zero_cnt_kernel<<<118, 256>>>();
    mega_prep<<<2368, 256>>>(w1, root1, w2, root2, x_src, x_dst, ei, et, E);
    scatter_kernel<<<(E + 7) / 8, 256>>>(ei, et, E);

    fused_all<<<GRID_M, THREADS, SMEM_T>>>(b1, b2, out);
}